// round 1
// baseline (speedup 1.0000x reference)
#include <cuda_runtime.h>
#include <cstdint>

#define HH 512
#define WW 512
#define MAXB 16

// unit length per (batch, row) and its square — computed by unit_kernel,
// consumed by size_kernel. Device globals (no allocation allowed).
__device__ float g_unit [MAXB * HH];
__device__ float g_unit2[MAXB * HH];

// ---------------------------------------------------------------------------
// Kernel 1: per-image road-width fit  ->  unit[h] = 3.25 / width(h)
// One block per batch image, 512 threads (= H rows).
// ---------------------------------------------------------------------------
__global__ void __launch_bounds__(512) unit_kernel(const float* __restrict__ seg)
{
    const int b    = blockIdx.x;
    const int tid  = threadIdx.x;
    const int lane = tid & 31;
    const int warp = tid >> 5;

    __shared__ float         s_xmin[HH];
    __shared__ float         s_xmax[HH];
    __shared__ unsigned char s_valid[HH];

    const float* img = seg + (size_t)b * HH * WW * 2;

    // Phase 1: warp per row -> min/max positive column (channel 1).
    for (int h = warp; h < HH; h += 16) {
        int mn = WW, mx = -1;
        const float* row = img + (size_t)h * WW * 2;
        for (int w = lane; w < WW; w += 32) {
            float v = row[2 * w + 1];
            if (v > 0.0f) { mn = min(mn, w); mx = max(mx, w); }
        }
        #pragma unroll
        for (int o = 16; o; o >>= 1) {
            mn = min(mn, __shfl_down_sync(0xffffffffu, mn, o));
            mx = max(mx, __shfl_down_sync(0xffffffffu, mx, o));
        }
        if (lane == 0) {
            s_xmin[h]  = (float)mn;
            s_xmax[h]  = (float)mx;
            s_valid[h] = (mx >= 0 && mn != mx) ? 1 : 0;
        }
    }
    __syncthreads();

    // Phase 2: rank among valid rows (ballot prefix) + trimmed keep mask.
    __shared__ int wtot[16];
    const int valid = (int)s_valid[tid];
    unsigned bal = __ballot_sync(0xffffffffu, valid);
    int pre = __popc(bal & ((1u << lane) - 1u));
    if (lane == 0) wtot[warp] = __popc(bal);
    __syncthreads();

    int off = 0, nvalid = 0;
    #pragma unroll
    for (int i = 0; i < 16; i++) {
        int t = wtot[i];
        nvalid += t;
        if (i < warp) off += t;
    }
    const int rank = off + pre;

    int drop = (int)((float)nvalid * 0.15f);   // trunc, matches astype(int32)
    if (drop < 1) drop = 1;
    const int keep = valid && (rank >= drop) && (rank < nvalid - drop);

    // Phase 3: weighted LS sums (7 scalars) via warp reduce + shared atomics.
    const float w  = keep ? 1.0f : 0.0f;
    const float y  = (float)tid;
    const float xl = s_xmin[tid];
    const float xr = s_xmax[tid];

    float v0 = w;
    float v1 = w * y;
    float v2 = w * y * y;
    float v3 = w * xl;
    float v4 = w * y * xl;
    float v5 = w * xr;
    float v6 = w * y * xr;

    __shared__ float acc[7];
    if (tid < 7) acc[tid] = 0.0f;
    __syncthreads();

    #pragma unroll
    for (int o = 16; o; o >>= 1) {
        v0 += __shfl_down_sync(0xffffffffu, v0, o);
        v1 += __shfl_down_sync(0xffffffffu, v1, o);
        v2 += __shfl_down_sync(0xffffffffu, v2, o);
        v3 += __shfl_down_sync(0xffffffffu, v3, o);
        v4 += __shfl_down_sync(0xffffffffu, v4, o);
        v5 += __shfl_down_sync(0xffffffffu, v5, o);
        v6 += __shfl_down_sync(0xffffffffu, v6, o);
    }
    if (lane == 0) {
        atomicAdd(&acc[0], v0);
        atomicAdd(&acc[1], v1);
        atomicAdd(&acc[2], v2);
        atomicAdd(&acc[3], v3);
        atomicAdd(&acc[4], v4);
        atomicAdd(&acc[5], v5);
        atomicAdd(&acc[6], v6);
    }
    __syncthreads();

    const float Sw  = acc[0], Sy  = acc[1], Syy = acc[2];
    const float Sxl = acc[3], Sxyl = acc[4];
    const float Sxr = acc[5], Sxyr = acc[6];

    const float det  = Syy * Sw - Sy * Sy;
    const float safe = (det > 0.0f) ? det : 1.0f;

    float sl_l = (Sw * Sxyl - Sy * Sxl) / safe;
    float ic_l = (-Sy * Sxyl + Syy * Sxl) / safe;
    float sl_r = (Sw * Sxyr - Sy * Sxr) / safe;
    float ic_r = (-Sy * Sxyr + Syy * Sxr) / safe;
    if (!(det > 0.0f)) { sl_l = ic_l = sl_r = ic_r = 0.0f; }

    float width = (y * sl_r + ic_r) - (y * sl_l + ic_l);
    width = fmaxf(width, 1.0f);
    const float u = 3.25f / width;

    g_unit [b * HH + tid] = u;
    g_unit2[b * HH + tid] = u * u;
}

// ---------------------------------------------------------------------------
// Kernel 2: one block per (b, n). Streams the [H, W] slab once.
//   instance   = sum_{h,w} unit2[h] * pad
//   horizontal = max_w sum_h unit[h] * pad
//   vertical   = sum_h unit[h] * any_w(pad > 0.5)
// ---------------------------------------------------------------------------
__global__ void __launch_bounds__(512) size_kernel(const float* __restrict__ pad,
                                                   float* __restrict__ out,
                                                   int N)
{
    const int bn   = blockIdx.x;
    const int b    = bn / N;
    const int tid  = threadIdx.x;       // thread t owns column t
    const int lane = tid & 31;
    const int warp = tid >> 5;

    __shared__ float    su [HH];
    __shared__ float    su2[HH];
    __shared__ unsigned anymask[HH / 32];
    __shared__ float    sred[16];

    su [tid] = g_unit [b * HH + tid];
    su2[tid] = g_unit2[b * HH + tid];
    if (tid < HH / 32) anymask[tid] = 0u;
    __syncthreads();

    const float* p = pad + (size_t)bn * HH * WW;

    float colacc = 0.0f;   // sum_h unit[h]  * pad[h, tid]
    float inst   = 0.0f;   // sum_h unit2[h] * pad[h, tid]
    unsigned lm[HH / 32];
    #pragma unroll
    for (int i = 0; i < HH / 32; i++) lm[i] = 0u;

    #pragma unroll 8
    for (int h = 0; h < HH; h++) {
        const float v = p[(size_t)h * WW + tid];
        colacc = fmaf(su [h], v, colacc);
        inst   = fmaf(su2[h], v, inst);
        if (v > 0.5f) lm[h >> 5] |= (1u << (h & 31));
    }

    // OR per-column "row occupied" bits into the shared per-row mask.
    #pragma unroll
    for (int i = 0; i < HH / 32; i++) {
        unsigned m = __reduce_or_sync(0xffffffffu, lm[i]);
        if (lane == 0 && m) atomicOr(&anymask[i], m);
    }

    // --- reduce 1: instance (sum) ---
    float s = inst;
    #pragma unroll
    for (int o = 16; o; o >>= 1) s += __shfl_down_sync(0xffffffffu, s, o);
    if (lane == 0) sred[warp] = s;
    __syncthreads();
    if (tid == 0) {
        float t = 0.0f;
        #pragma unroll
        for (int i = 0; i < 16; i++) t += sred[i];
        out[bn * 3 + 0] = t;
    }
    __syncthreads();

    // --- reduce 2: horizontal (max over columns) ---
    float m = colacc;
    #pragma unroll
    for (int o = 16; o; o >>= 1) m = fmaxf(m, __shfl_down_sync(0xffffffffu, m, o));
    if (lane == 0) sred[warp] = m;
    __syncthreads();
    if (tid == 0) {
        float t = sred[0];
        #pragma unroll
        for (int i = 1; i < 16; i++) t = fmaxf(t, sred[i]);
        out[bn * 3 + 1] = t;
    }
    __syncthreads();

    // --- reduce 3: vertical (sum over occupied rows) ---
    const unsigned bit = (anymask[tid >> 5] >> (tid & 31)) & 1u;
    float vv = bit ? su[tid] : 0.0f;
    #pragma unroll
    for (int o = 16; o; o >>= 1) vv += __shfl_down_sync(0xffffffffu, vv, o);
    if (lane == 0) sred[warp] = vv;
    __syncthreads();
    if (tid == 0) {
        float t = 0.0f;
        #pragma unroll
        for (int i = 0; i < 16; i++) t += sred[i];
        out[bn * 3 + 2] = t;
    }
}

// ---------------------------------------------------------------------------
extern "C" void kernel_launch(void* const* d_in, const int* in_sizes, int n_in,
                              void* d_out, int out_size)
{
    const float* seg = (const float*)d_in[0];   // [B, H, W, 2]
    const float* pad = (const float*)d_in[1];   // [B, N, H, W]
    float* out = (float*)d_out;                 // [B, N, 3]

    const int B = in_sizes[0] / (HH * WW * 2);
    const int N = in_sizes[1] / (B * HH * WW);

    unit_kernel<<<B, 512>>>(seg);
    size_kernel<<<B * N, 512>>>(pad, out, N);
}

// round 2
// speedup vs baseline: 3.3851x; 3.3851x over previous
#include <cuda_runtime.h>
#include <cstdint>

#define HH 512
#define WW 512
#define MAXB 16

// Scratch (device globals — no allocation allowed).
__device__ int   g_xmin [MAXB * HH];
__device__ int   g_xmax [MAXB * HH];
__device__ float g_unit [MAXB * HH];
__device__ float g_unit2[MAXB * HH];

// ---------------------------------------------------------------------------
// Kernel A: per-row min/max positive column of seg channel 1.
// Grid = B*16 blocks; each block handles 32 rows; warp handles 2 rows.
// float2 loads -> fully coalesced 256B per warp-instruction.
// ---------------------------------------------------------------------------
__global__ void __launch_bounds__(512) minmax_kernel(const float* __restrict__ seg)
{
    const int b       = blockIdx.x >> 4;
    const int rowbase = (blockIdx.x & 15) * 32;
    const int lane    = threadIdx.x & 31;
    const int warp    = threadIdx.x >> 5;

    const float2* img = (const float2*)(seg + (size_t)b * HH * WW * 2);

    #pragma unroll
    for (int rr = 0; rr < 2; rr++) {
        const int h = rowbase + warp + rr * 16;
        const float2* row = img + (size_t)h * WW;
        int mn = WW, mx = -1;
        #pragma unroll 4
        for (int w = lane; w < WW; w += 32) {
            float v = row[w].y;           // channel 1
            if (v > 0.0f) { mn = min(mn, w); mx = max(mx, w); }
        }
        #pragma unroll
        for (int o = 16; o; o >>= 1) {
            mn = min(mn, __shfl_down_sync(0xffffffffu, mn, o));
            mx = max(mx, __shfl_down_sync(0xffffffffu, mx, o));
        }
        if (lane == 0) {
            g_xmin[b * HH + h] = mn;
            g_xmax[b * HH + h] = mx;
        }
    }
}

// ---------------------------------------------------------------------------
// Kernel B: trimmed weighted least-squares fit -> unit[h]. Grid = B, tiny.
// ---------------------------------------------------------------------------
__global__ void __launch_bounds__(512) fit_kernel()
{
    const int b    = blockIdx.x;
    const int tid  = threadIdx.x;
    const int lane = tid & 31;
    const int warp = tid >> 5;

    const int xmin_i = g_xmin[b * HH + tid];
    const int xmax_i = g_xmax[b * HH + tid];
    const int valid  = (xmax_i >= 0 && xmin_i != xmax_i) ? 1 : 0;

    // rank among valid rows
    __shared__ int wtot[16];
    unsigned bal = __ballot_sync(0xffffffffu, valid);
    int pre = __popc(bal & ((1u << lane) - 1u));
    if (lane == 0) wtot[warp] = __popc(bal);
    __syncthreads();

    int off = 0, nvalid = 0;
    #pragma unroll
    for (int i = 0; i < 16; i++) {
        int t = wtot[i];
        nvalid += t;
        if (i < warp) off += t;
    }
    const int rank = off + pre;

    int drop = (int)((float)nvalid * 0.15f);   // trunc, matches astype(int32)
    if (drop < 1) drop = 1;
    const int keep = valid && (rank >= drop) && (rank < nvalid - drop);

    const float w  = keep ? 1.0f : 0.0f;
    const float y  = (float)tid;
    const float xl = (float)xmin_i;
    const float xr = (float)xmax_i;

    float v0 = w;
    float v1 = w * y;
    float v2 = w * y * y;
    float v3 = w * xl;
    float v4 = w * y * xl;
    float v5 = w * xr;
    float v6 = w * y * xr;

    __shared__ float acc[7];
    if (tid < 7) acc[tid] = 0.0f;
    __syncthreads();

    #pragma unroll
    for (int o = 16; o; o >>= 1) {
        v0 += __shfl_down_sync(0xffffffffu, v0, o);
        v1 += __shfl_down_sync(0xffffffffu, v1, o);
        v2 += __shfl_down_sync(0xffffffffu, v2, o);
        v3 += __shfl_down_sync(0xffffffffu, v3, o);
        v4 += __shfl_down_sync(0xffffffffu, v4, o);
        v5 += __shfl_down_sync(0xffffffffu, v5, o);
        v6 += __shfl_down_sync(0xffffffffu, v6, o);
    }
    if (lane == 0) {
        atomicAdd(&acc[0], v0);
        atomicAdd(&acc[1], v1);
        atomicAdd(&acc[2], v2);
        atomicAdd(&acc[3], v3);
        atomicAdd(&acc[4], v4);
        atomicAdd(&acc[5], v5);
        atomicAdd(&acc[6], v6);
    }
    __syncthreads();

    const float Sw  = acc[0], Sy  = acc[1], Syy = acc[2];
    const float Sxl = acc[3], Sxyl = acc[4];
    const float Sxr = acc[5], Sxyr = acc[6];

    const float det  = Syy * Sw - Sy * Sy;
    const float safe = (det > 0.0f) ? det : 1.0f;

    float sl_l = (Sw * Sxyl - Sy * Sxl) / safe;
    float ic_l = (-Sy * Sxyl + Syy * Sxl) / safe;
    float sl_r = (Sw * Sxyr - Sy * Sxr) / safe;
    float ic_r = (-Sy * Sxyr + Syy * Sxr) / safe;
    if (!(det > 0.0f)) { sl_l = ic_l = sl_r = ic_r = 0.0f; }

    float width = (y * sl_r + ic_r) - (y * sl_l + ic_l);
    width = fmaxf(width, 1.0f);
    const float u = 3.25f / width;

    g_unit [b * HH + tid] = u;
    g_unit2[b * HH + tid] = u * u;
}

// ---------------------------------------------------------------------------
// Kernel C: one block per (b, n). float4 streaming of the [H, W] slab.
// 512 threads = 4 row-groups x 128 threads; thread (g,c) owns columns
// 4c..4c+3, rows h = g, g+4, ..., 508 (128 iterations).
//   instance   = sum_{h,w} unit2[h] * pad
//   horizontal = max_w sum_h unit[h] * pad
//   vertical   = sum_h unit[h] * any_w(pad > 0.5)
// ---------------------------------------------------------------------------
__global__ void __launch_bounds__(512) size_kernel(const float* __restrict__ pad,
                                                   float* __restrict__ out,
                                                   int N)
{
    const int bn   = blockIdx.x;
    const int b    = bn / N;
    const int tid  = threadIdx.x;
    const int lane = tid & 31;
    const int warp = tid >> 5;
    const int g    = tid >> 7;        // row group 0..3
    const int c    = tid & 127;       // column group: columns 4c..4c+3

    __shared__ float    su [HH];
    __shared__ float    su2[HH];
    __shared__ float    scol[WW];     // per-column sum_h unit[h]*v
    __shared__ unsigned grpmask[4][4];// per-group 128-bit row-occupied mask
    __shared__ float    sred[16];

    su [tid] = g_unit [b * HH + tid];
    su2[tid] = g_unit2[b * HH + tid];
    scol[tid & (WW - 1)] = 0.0f;
    if (tid < 16) ((unsigned*)grpmask)[tid] = 0u;
    __syncthreads();

    const float4* p = (const float4*)(pad + (size_t)bn * HH * WW) + c;

    float4 colacc = make_float4(0.f, 0.f, 0.f, 0.f);
    float  inst   = 0.0f;
    unsigned lm[4] = {0u, 0u, 0u, 0u};

    #pragma unroll 8
    for (int k = 0; k < 128; k++) {
        const int h = g + 4 * k;
        const float4 v = p[(size_t)h * (WW / 4)];
        const float u1 = su[h], u2 = su2[h];
        colacc.x = fmaf(u1, v.x, colacc.x);
        colacc.y = fmaf(u1, v.y, colacc.y);
        colacc.z = fmaf(u1, v.z, colacc.z);
        colacc.w = fmaf(u1, v.w, colacc.w);
        inst = fmaf(u2, (v.x + v.y) + (v.z + v.w), inst);
        if (v.x > 0.5f || v.y > 0.5f || v.z > 0.5f || v.w > 0.5f)
            lm[k >> 5] |= (1u << (k & 31));
    }

    // row-occupied bits: OR across the 4 warps of this group
    #pragma unroll
    for (int i = 0; i < 4; i++) {
        unsigned m = __reduce_or_sync(0xffffffffu, lm[i]);
        if (lane == 0 && m) atomicOr(&grpmask[g][i], m);
    }

    // per-column sums: combine 4 groups (4-way shared atomics)
    atomicAdd(&scol[4 * c + 0], colacc.x);
    atomicAdd(&scol[4 * c + 1], colacc.y);
    atomicAdd(&scol[4 * c + 2], colacc.z);
    atomicAdd(&scol[4 * c + 3], colacc.w);

    // --- reduce 1: instance (sum) ---
    float s = inst;
    #pragma unroll
    for (int o = 16; o; o >>= 1) s += __shfl_down_sync(0xffffffffu, s, o);
    if (lane == 0) sred[warp] = s;
    __syncthreads();
    if (tid == 0) {
        float t = 0.0f;
        #pragma unroll
        for (int i = 0; i < 16; i++) t += sred[i];
        out[bn * 3 + 0] = t;
    }
    __syncthreads();

    // --- reduce 2: horizontal (max over columns) ---
    float m = scol[tid];
    #pragma unroll
    for (int o = 16; o; o >>= 1) m = fmaxf(m, __shfl_down_sync(0xffffffffu, m, o));
    if (lane == 0) sred[warp] = m;
    __syncthreads();
    if (tid == 0) {
        float t = sred[0];
        #pragma unroll
        for (int i = 1; i < 16; i++) t = fmaxf(t, sred[i]);
        out[bn * 3 + 1] = t;
    }
    __syncthreads();

    // --- reduce 3: vertical (sum of unit over occupied rows) ---
    // row h was handled by group h&3, iteration k = h>>2
    const int hk = tid >> 2;
    const unsigned bit = (grpmask[tid & 3][hk >> 5] >> (hk & 31)) & 1u;
    float vv = bit ? su[tid] : 0.0f;
    #pragma unroll
    for (int o = 16; o; o >>= 1) vv += __shfl_down_sync(0xffffffffu, vv, o);
    if (lane == 0) sred[warp] = vv;
    __syncthreads();
    if (tid == 0) {
        float t = 0.0f;
        #pragma unroll
        for (int i = 0; i < 16; i++) t += sred[i];
        out[bn * 3 + 2] = t;
    }
}

// ---------------------------------------------------------------------------
extern "C" void kernel_launch(void* const* d_in, const int* in_sizes, int n_in,
                              void* d_out, int out_size)
{
    const float* seg = (const float*)d_in[0];   // [B, H, W, 2]
    const float* pad = (const float*)d_in[1];   // [B, N, H, W]
    float* out = (float*)d_out;                 // [B, N, 3]

    const int B = in_sizes[0] / (HH * WW * 2);
    const int N = in_sizes[1] / (B * HH * WW);

    minmax_kernel<<<B * 16, 512>>>(seg);
    fit_kernel<<<B, 512>>>();
    size_kernel<<<B * N, 512>>>(pad, out, N);
}

// round 3
// speedup vs baseline: 3.4915x; 1.0314x over previous
#include <cuda_runtime.h>
#include <cstdint>

#define HH 512
#define WW 512
#define MAXB 16

// Scratch (device globals — no allocation allowed).
__device__ int   g_xmin [MAXB * HH];
__device__ int   g_xmax [MAXB * HH];
__device__ float g_unit [MAXB * HH];
__device__ float g_unit2[MAXB * HH];
__device__ int   g_count[MAXB];        // zero-init at load; reset after each use

// ---------------------------------------------------------------------------
// Kernel A: per-row min/max positive column of seg channel 1, fused with the
// trimmed weighted-LS fit (done by the last block to finish per image).
// Grid = B*32 blocks; block = 512 thr = 16 warps; each warp owns one row.
// Row = 512 px * 2 ch = 4KB -> 256 float4 -> 8 float4 per lane (MLP=8).
// ---------------------------------------------------------------------------
__global__ void __launch_bounds__(512) minmax_fit_kernel(const float* __restrict__ seg)
{
    const int b    = blockIdx.x >> 5;
    const int blk  = blockIdx.x & 31;
    const int tid  = threadIdx.x;
    const int lane = tid & 31;
    const int warp = tid >> 5;

    const int h = blk * 16 + warp;
    const float4* row = (const float4*)(seg + (size_t)b * HH * WW * 2
                                            + (size_t)h * WW * 2);
    int mn = WW, mx = -1;
    #pragma unroll
    for (int i = 0; i < 8; i++) {
        const int j = lane + i * 32;        // float4 index 0..255
        const float4 v = row[j];            // pixels 2j (x=ch0,y=ch1), 2j+1 (z,w)
        const int p0 = 2 * j, p1 = 2 * j + 1;
        if (v.y > 0.0f) { mn = min(mn, p0); mx = max(mx, p0); }
        if (v.w > 0.0f) { mn = min(mn, p1); mx = max(mx, p1); }
    }
    #pragma unroll
    for (int o = 16; o; o >>= 1) {
        mn = min(mn, __shfl_down_sync(0xffffffffu, mn, o));
        mx = max(mx, __shfl_down_sync(0xffffffffu, mx, o));
    }
    if (lane == 0) {
        g_xmin[b * HH + h] = mn;
        g_xmax[b * HH + h] = mx;
    }

    // ---- elect the last block of this image to run the fit ----
    __shared__ int isLast;
    __syncthreads();
    if (tid == 0) {
        __threadfence();
        isLast = (atomicAdd(&g_count[b], 1) == 31);
    }
    __syncthreads();
    if (!isLast) return;

    // ---- fit phase: tid = row index; read via L2 (skip possibly-stale L1) ----
    const int xmin_i = __ldcg(&g_xmin[b * HH + tid]);
    const int xmax_i = __ldcg(&g_xmax[b * HH + tid]);
    const int valid  = (xmax_i >= 0 && xmin_i != xmax_i) ? 1 : 0;

    __shared__ int wtot[16];
    unsigned bal = __ballot_sync(0xffffffffu, valid);
    int pre = __popc(bal & ((1u << lane) - 1u));
    if (lane == 0) wtot[warp] = __popc(bal);
    __syncthreads();

    int off = 0, nvalid = 0;
    #pragma unroll
    for (int i = 0; i < 16; i++) {
        int t = wtot[i];
        nvalid += t;
        if (i < warp) off += t;
    }
    const int rank = off + pre;

    int drop = (int)((float)nvalid * 0.15f);   // trunc, matches astype(int32)
    if (drop < 1) drop = 1;
    const int keep = valid && (rank >= drop) && (rank < nvalid - drop);

    const float w  = keep ? 1.0f : 0.0f;
    const float y  = (float)tid;
    const float xl = (float)xmin_i;
    const float xr = (float)xmax_i;

    float v0 = w;
    float v1 = w * y;
    float v2 = w * y * y;
    float v3 = w * xl;
    float v4 = w * y * xl;
    float v5 = w * xr;
    float v6 = w * y * xr;

    __shared__ float acc[7];
    if (tid < 7) acc[tid] = 0.0f;
    __syncthreads();

    #pragma unroll
    for (int o = 16; o; o >>= 1) {
        v0 += __shfl_down_sync(0xffffffffu, v0, o);
        v1 += __shfl_down_sync(0xffffffffu, v1, o);
        v2 += __shfl_down_sync(0xffffffffu, v2, o);
        v3 += __shfl_down_sync(0xffffffffu, v3, o);
        v4 += __shfl_down_sync(0xffffffffu, v4, o);
        v5 += __shfl_down_sync(0xffffffffu, v5, o);
        v6 += __shfl_down_sync(0xffffffffu, v6, o);
    }
    if (lane == 0) {
        atomicAdd(&acc[0], v0);
        atomicAdd(&acc[1], v1);
        atomicAdd(&acc[2], v2);
        atomicAdd(&acc[3], v3);
        atomicAdd(&acc[4], v4);
        atomicAdd(&acc[5], v5);
        atomicAdd(&acc[6], v6);
    }
    __syncthreads();

    const float Sw  = acc[0], Sy  = acc[1], Syy = acc[2];
    const float Sxl = acc[3], Sxyl = acc[4];
    const float Sxr = acc[5], Sxyr = acc[6];

    const float det  = Syy * Sw - Sy * Sy;
    const float safe = (det > 0.0f) ? det : 1.0f;

    float sl_l = (Sw * Sxyl - Sy * Sxl) / safe;
    float ic_l = (-Sy * Sxyl + Syy * Sxl) / safe;
    float sl_r = (Sw * Sxyr - Sy * Sxr) / safe;
    float ic_r = (-Sy * Sxyr + Syy * Sxr) / safe;
    if (!(det > 0.0f)) { sl_l = ic_l = sl_r = ic_r = 0.0f; }

    float width = (y * sl_r + ic_r) - (y * sl_l + ic_l);
    width = fmaxf(width, 1.0f);
    const float u = 3.25f / width;

    g_unit [b * HH + tid] = u;
    g_unit2[b * HH + tid] = u * u;

    if (tid == 0) g_count[b] = 0;    // reset for the next graph replay
}

// ---------------------------------------------------------------------------
// Kernel C: one block per (b, n). float4 streaming of the [H, W] slab.
// 512 threads = 4 row-groups x 128 threads; thread (g,c) owns columns
// 4c..4c+3, rows h = g, g+4, ..., 508 (128 iterations).
//   instance   = sum_{h,w} unit2[h] * pad
//   horizontal = max_w sum_h unit[h] * pad
//   vertical   = sum_h unit[h] * any_w(pad > 0.5)
// ---------------------------------------------------------------------------
__global__ void __launch_bounds__(512) size_kernel(const float* __restrict__ pad,
                                                   float* __restrict__ out,
                                                   int N)
{
    const int bn   = blockIdx.x;
    const int b    = bn / N;
    const int tid  = threadIdx.x;
    const int lane = tid & 31;
    const int warp = tid >> 5;
    const int g    = tid >> 7;        // row group 0..3
    const int c    = tid & 127;       // column group: columns 4c..4c+3

    __shared__ float    su [HH];
    __shared__ float    su2[HH];
    __shared__ float    scol[WW];     // per-column sum_h unit[h]*v
    __shared__ unsigned grpmask[4][4];// per-group 128-bit row-occupied mask
    __shared__ float    sred[16];

    su [tid] = g_unit [b * HH + tid];
    su2[tid] = g_unit2[b * HH + tid];
    scol[tid & (WW - 1)] = 0.0f;
    if (tid < 16) ((unsigned*)grpmask)[tid] = 0u;
    __syncthreads();

    const float4* p = (const float4*)(pad + (size_t)bn * HH * WW) + c;

    float4 colacc = make_float4(0.f, 0.f, 0.f, 0.f);
    float  inst   = 0.0f;
    unsigned lm[4] = {0u, 0u, 0u, 0u};

    #pragma unroll 8
    for (int k = 0; k < 128; k++) {
        const int h = g + 4 * k;
        const float4 v = p[(size_t)h * (WW / 4)];
        const float u1 = su[h], u2 = su2[h];
        colacc.x = fmaf(u1, v.x, colacc.x);
        colacc.y = fmaf(u1, v.y, colacc.y);
        colacc.z = fmaf(u1, v.z, colacc.z);
        colacc.w = fmaf(u1, v.w, colacc.w);
        inst = fmaf(u2, (v.x + v.y) + (v.z + v.w), inst);
        if (v.x > 0.5f || v.y > 0.5f || v.z > 0.5f || v.w > 0.5f)
            lm[k >> 5] |= (1u << (k & 31));
    }

    // row-occupied bits: OR across the 4 warps of this group
    #pragma unroll
    for (int i = 0; i < 4; i++) {
        unsigned m = __reduce_or_sync(0xffffffffu, lm[i]);
        if (lane == 0 && m) atomicOr(&grpmask[g][i], m);
    }

    // per-column sums: combine 4 groups (4-way shared atomics)
    atomicAdd(&scol[4 * c + 0], colacc.x);
    atomicAdd(&scol[4 * c + 1], colacc.y);
    atomicAdd(&scol[4 * c + 2], colacc.z);
    atomicAdd(&scol[4 * c + 3], colacc.w);

    // --- reduce 1: instance (sum) ---
    float s = inst;
    #pragma unroll
    for (int o = 16; o; o >>= 1) s += __shfl_down_sync(0xffffffffu, s, o);
    if (lane == 0) sred[warp] = s;
    __syncthreads();
    if (tid == 0) {
        float t = 0.0f;
        #pragma unroll
        for (int i = 0; i < 16; i++) t += sred[i];
        out[bn * 3 + 0] = t;
    }
    __syncthreads();

    // --- reduce 2: horizontal (max over columns) ---
    float m = scol[tid];
    #pragma unroll
    for (int o = 16; o; o >>= 1) m = fmaxf(m, __shfl_down_sync(0xffffffffu, m, o));
    if (lane == 0) sred[warp] = m;
    __syncthreads();
    if (tid == 0) {
        float t = sred[0];
        #pragma unroll
        for (int i = 1; i < 16; i++) t = fmaxf(t, sred[i]);
        out[bn * 3 + 1] = t;
    }
    __syncthreads();

    // --- reduce 3: vertical (sum of unit over occupied rows) ---
    // row h was handled by group h&3, iteration k = h>>2
    const int hk = tid >> 2;
    const unsigned bit = (grpmask[tid & 3][hk >> 5] >> (hk & 31)) & 1u;
    float vv = bit ? su[tid] : 0.0f;
    #pragma unroll
    for (int o = 16; o; o >>= 1) vv += __shfl_down_sync(0xffffffffu, vv, o);
    if (lane == 0) sred[warp] = vv;
    __syncthreads();
    if (tid == 0) {
        float t = 0.0f;
        #pragma unroll
        for (int i = 0; i < 16; i++) t += sred[i];
        out[bn * 3 + 2] = t;
    }
}

// ---------------------------------------------------------------------------
extern "C" void kernel_launch(void* const* d_in, const int* in_sizes, int n_in,
                              void* d_out, int out_size)
{
    const float* seg = (const float*)d_in[0];   // [B, H, W, 2]
    const float* pad = (const float*)d_in[1];   // [B, N, H, W]
    float* out = (float*)d_out;                 // [B, N, 3]

    const int B = in_sizes[0] / (HH * WW * 2);
    const int N = in_sizes[1] / (B * HH * WW);

    minmax_fit_kernel<<<B * 32, 512>>>(seg);
    size_kernel<<<B * N, 512>>>(pad, out, N);
}